// round 8
// baseline (speedup 1.0000x reference)
#include <cuda_runtime.h>
#include <cuda_fp16.h>
#include <cstdint>

#define B 8192
#define D 256
#define NT 64
#define NCTA (NT * (NT + 1) / 2)  // 2080 upper-triangular tiles

typedef unsigned long long u64;

__device__ __half g_xh[B * D];
__device__ float g_invnorm[B];
__device__ u64 g_pos_pack[B];    // ((bits(posmax+1))<<32)|idx ; 0 = none
__device__ u64 g_neg_pack[B];    // ((bits(negmin))<<32)|idx ; ~0 = none
__device__ float g_sum;
__device__ int   g_cnt;
__device__ unsigned int g_done;

// ---- dynamic smem layout (bytes)
#define SM_A     0                 // 8 slabs x [128][32] halves = 65536
#define SM_B0    65536             // 8192
#define SM_B1    73728             // 8192
#define SM_JLAB  81920             // 512
#define SM_RPV   82432             // [2][128]
#define SM_RPI   83456
#define SM_RNV   84480
#define SM_RNI   85504
#define SM_CPV   86528             // [4][128]
#define SM_CPI   88576
#define SM_CNV   90624
#define SM_CNI   92672
#define SMEM_TOTAL 94720

__device__ __forceinline__ uint32_t smem_u32(const void* p) {
    uint32_t a;
    asm("{ .reg .u64 t; cvta.to.shared.u64 t, %1; cvt.u32.u64 %0, t; }" : "=r"(a) : "l"(p));
    return a;
}

__device__ __forceinline__ uint32_t swz(int r, int c) {
    return (uint32_t)(r * 64 + ((c ^ ((r >> 1) & 3)) << 4));
}

#define CP_ASYNC16(dst, src) \
    asm volatile("cp.async.cg.shared.global [%0], [%1], 16;" :: "r"(dst), "l"(src) : "memory")
#define CP_COMMIT() asm volatile("cp.async.commit_group;" ::: "memory")

__device__ __forceinline__ void ldsm_x4(uint32_t* f, uint32_t addr) {
    asm volatile("ldmatrix.sync.aligned.m8n8.x4.shared.b16 {%0,%1,%2,%3}, [%4];"
                 : "=r"(f[0]), "=r"(f[1]), "=r"(f[2]), "=r"(f[3]) : "r"(addr));
}

// fp16-ACCUMULATE mma: d is 2 x .f16x2 registers
__device__ __forceinline__ void mma16816_h(uint32_t* d, const uint32_t* a, uint32_t b0, uint32_t b1) {
    asm volatile(
        "mma.sync.aligned.m16n8k16.row.col.f16.f16.f16.f16 "
        "{%0,%1}, {%2,%3,%4,%5}, {%6,%7}, {%0,%1};"
        : "+r"(d[0]), "+r"(d[1])
        : "r"(a[0]), "r"(a[1]), "r"(a[2]), "r"(a[3]), "r"(b0), "r"(b1));
}

__device__ __forceinline__ void redmaxi(float& v, int& i, int off) {
    const float ov = __shfl_xor_sync(0xffffffffu, v, off);
    const int oi = __shfl_xor_sync(0xffffffffu, i, off);
    if (ov > v) { v = ov; i = oi; }
}
__device__ __forceinline__ void redmini(float& v, int& i, int off) {
    const float ov = __shfl_xor_sync(0xffffffffu, v, off);
    const int oi = __shfl_xor_sync(0xffffffffu, i, off);
    if (ov < v) { v = ov; i = oi; }
}

__device__ __forceinline__ u64 packmax(float v, int i) {
    return ((u64)__float_as_uint(v + 1.0f) << 32) | (uint32_t)i;
}
__device__ __forceinline__ u64 packmin(float v, int i) {
    return ((u64)__float_as_uint(v) << 32) | (uint32_t)i;
}

// ====================== 1) normalize -> fp16 + init ======================
__global__ void normalize_kernel(const float* __restrict__ x) {
    const int gid = blockIdx.x * 256 + threadIdx.x;
    if (gid < B) {
        g_pos_pack[gid] = 0ull;
        g_neg_pack[gid] = 0xFFFFFFFFFFFFFFFFull;
    }
    if (gid == 0) { g_sum = 0.0f; g_cnt = 0; g_done = 0u; }

    const int row = gid >> 5;
    const int lane = threadIdx.x & 31;
    const float4* src = (const float4*)&x[(size_t)row * D];
    float4 a = src[lane];
    float4 b = src[lane + 32];
    float s = a.x*a.x + a.y*a.y + a.z*a.z + a.w*a.w
            + b.x*b.x + b.y*b.y + b.z*b.z + b.w*b.w;
    #pragma unroll
    for (int o = 16; o > 0; o >>= 1) s += __shfl_xor_sync(0xffffffffu, s, o);
    const float inv = 1.0f / fmaxf(sqrtf(s), 1e-12f);
    if (lane == 0) g_invnorm[row] = inv;
    __half2* dst = (__half2*)&g_xh[(size_t)row * D];
    dst[lane*2 + 0]  = __floats2half2_rn(a.x * inv, a.y * inv);
    dst[lane*2 + 1]  = __floats2half2_rn(a.z * inv, a.w * inv);
    dst[lane*2 + 64] = __floats2half2_rn(b.x * inv, b.y * inv);
    dst[lane*2 + 65] = __floats2half2_rn(b.z * inv, b.w * inv);
}

// ====================== 2) upper-triangular tile kernel (fp16 accum + idx) ======================
__global__ __launch_bounds__(256, 2) void tile_kernel(const int* __restrict__ labels) {
    const int g = blockIdx.x;
    int ti = (int)((129.0f - sqrtf(16641.0f - 8.0f * (float)g)) * 0.5f);
    while ((ti + 1) * (129 - (ti + 1)) / 2 <= g) ti++;
    while (ti * (129 - ti) / 2 > g) ti--;
    const int tj = ti + (g - ti * (129 - ti) / 2);

    extern __shared__ char smem[];
    const uint32_t sb = smem_u32(smem);
    const int tid = threadIdx.x;
    const int lane = tid & 31, wid = tid >> 5;
    const int wm = wid & 3, wn = wid >> 2;     // warp grid 4(m) x 2(n)
    const int i0 = ti * 128;
    const int j0 = tj * 128;

    if (tid < 128) ((int*)(smem + SM_JLAB))[tid] = labels[j0 + tid];

    // ---- prologue: A tile into 8 k-slabs of [128][32]
    #pragma unroll
    for (int q = 0; q < 16; q++) {
        const int gg = q * 256 + tid;
        const int slab = gg >> 9, w = gg & 511, r = w >> 2, c = w & 3;
        CP_ASYNC16(sb + SM_A + slab * 8192 + swz(r, c),
                   &g_xh[(size_t)(i0 + r) * D + slab * 32 + c * 8]);
    }
    CP_COMMIT();

    // B slab kk=0 -> buf0
    #pragma unroll
    for (int q = 0; q < 2; q++) {
        const int w = q * 256 + tid, r = w >> 2, c = w & 3;
        CP_ASYNC16(sb + SM_B0 + swz(r, c), &g_xh[(size_t)(j0 + r) * D + c * 8]);
    }
    CP_COMMIT();

    // per-lane ldmatrix offsets
    const int lr = (lane & 7) + ((lane >> 3) & 1) * 8;
    const int lc = lane >> 4;
    uint32_t a_off[2][2], b_off[4][2];
    #pragma unroll
    for (int mi = 0; mi < 2; mi++) {
        const int rA = wm * 32 + mi * 16 + lr;
        #pragma unroll
        for (int ks = 0; ks < 2; ks++) a_off[mi][ks] = swz(rA, 2 * ks + lc);
    }
    #pragma unroll
    for (int pr = 0; pr < 4; pr++) {
        const int rB = wn * 64 + pr * 16 + lr;
        #pragma unroll
        for (int ks = 0; ks < 2; ks++) b_off[pr][ks] = swz(rB, 2 * ks + lc);
    }

    int labm[2][2];
    #pragma unroll
    for (int mi = 0; mi < 2; mi++)
        #pragma unroll
        for (int hb = 0; hb < 2; hb++)
            labm[mi][hb] = __ldg(&labels[i0 + wm * 32 + mi * 16 + hb * 8 + (lane >> 2)]);

    uint32_t d[2][8][2];
    #pragma unroll
    for (int mi = 0; mi < 2; mi++)
        #pragma unroll
        for (int ni = 0; ni < 8; ni++) { d[mi][ni][0] = 0u; d[mi][ni][1] = 0u; }

    #pragma unroll
    for (int kk = 0; kk < 8; kk++) {
        if (kk < 7) {
            const uint32_t buf = sb + ((kk & 1) ? SM_B0 : SM_B1);
            #pragma unroll
            for (int q = 0; q < 2; q++) {
                const int w = q * 256 + tid, r = w >> 2, c = w & 3;
                CP_ASYNC16(buf + swz(r, c),
                           &g_xh[(size_t)(j0 + r) * D + (kk + 1) * 32 + c * 8]);
            }
            CP_COMMIT();
            asm volatile("cp.async.wait_group 1;" ::: "memory");
        } else {
            asm volatile("cp.async.wait_group 0;" ::: "memory");
        }
        __syncthreads();

        const uint32_t sa = sb + SM_A + kk * 8192;
        const uint32_t sbuf = sb + ((kk & 1) ? SM_B1 : SM_B0);
        #pragma unroll
        for (int ks = 0; ks < 2; ks++) {
            uint32_t a[2][4];
            ldsm_x4(a[0], sa + a_off[0][ks]);
            ldsm_x4(a[1], sa + a_off[1][ks]);
            uint32_t bf[4][4];
            #pragma unroll
            for (int pr = 0; pr < 4; pr++) ldsm_x4(bf[pr], sbuf + b_off[pr][ks]);
            #pragma unroll
            for (int mi = 0; mi < 2; mi++)
                #pragma unroll
                for (int pr = 0; pr < 4; pr++)
                    #pragma unroll
                    for (int sub = 0; sub < 2; sub++)
                        mma16816_h(d[mi][pr * 2 + sub], a[mi], bf[pr][sub], bf[pr][sub + 2]);
        }
        __syncthreads();
    }

    // ================= epilogue: row + column mining with indices =================
    const int* jl = (const int*)(smem + SM_JLAB);
    float* scpv = (float*)(smem + SM_CPV);
    int*   scpi = (int*)(smem + SM_CPI);
    float* scnv = (float*)(smem + SM_CNV);
    int*   scni = (int*)(smem + SM_CNI);

    float rpv[2][2], rnv[2][2];
    int rpi[2][2], rni[2][2];
    #pragma unroll
    for (int mi = 0; mi < 2; mi++)
        #pragma unroll
        for (int hb = 0; hb < 2; hb++) {
            rpv[mi][hb] = -1e9f; rpi[mi][hb] = -1;
            rnv[mi][hb] = 1e9f;  rni[mi][hb] = -1;
        }

    #pragma unroll
    for (int ni = 0; ni < 8; ni++) {
        const int colb = wn * 64 + ni * 8 + (lane & 3) * 2;
        const int l0 = jl[colb], l1 = jl[colb + 1];
        const int n0 = j0 + colb;
        float cpv[2] = {-1e9f, -1e9f}, cnv[2] = {1e9f, 1e9f};
        int cpi[2] = {-1, -1}, cni[2] = {-1, -1};
        #pragma unroll
        for (int mi = 0; mi < 2; mi++) {
            #pragma unroll
            for (int hb = 0; hb < 2; hb++) {
                const __half2 h = *reinterpret_cast<const __half2*>(&d[mi][ni][hb]);
                const float v0 = __low2float(h), v1 = __high2float(h);
                const int m = i0 + wm * 32 + mi * 16 + hb * 8 + (lane >> 2);
                const int lm = labm[mi][hb];
                // c01 = 0
                {
                    const int n = n0;
                    const float dist = fmaxf(1.0f - v0, 0.0f);
                    if (l0 == lm) {
                        if (m != n) {
                            if (dist > rpv[mi][hb]) { rpv[mi][hb] = dist; rpi[mi][hb] = n; }
                            if (dist > cpv[0]) { cpv[0] = dist; cpi[0] = m; }
                        }
                    } else {
                        if (dist < rnv[mi][hb]) { rnv[mi][hb] = dist; rni[mi][hb] = n; }
                        if (dist < cnv[0]) { cnv[0] = dist; cni[0] = m; }
                    }
                }
                // c01 = 1
                {
                    const int n = n0 + 1;
                    const float dist = fmaxf(1.0f - v1, 0.0f);
                    if (l1 == lm) {
                        if (m != n) {
                            if (dist > rpv[mi][hb]) { rpv[mi][hb] = dist; rpi[mi][hb] = n; }
                            if (dist > cpv[1]) { cpv[1] = dist; cpi[1] = m; }
                        }
                    } else {
                        if (dist < rnv[mi][hb]) { rnv[mi][hb] = dist; rni[mi][hb] = n; }
                        if (dist < cnv[1]) { cnv[1] = dist; cni[1] = m; }
                    }
                }
            }
        }
        #pragma unroll
        for (int off = 4; off <= 16; off <<= 1) {
            redmaxi(cpv[0], cpi[0], off); redmaxi(cpv[1], cpi[1], off);
            redmini(cnv[0], cni[0], off); redmini(cnv[1], cni[1], off);
        }
        if (lane < 4) {
            const int cidx = wn * 64 + ni * 8 + lane * 2;
            scpv[wm * 128 + cidx] = cpv[0]; scpi[wm * 128 + cidx] = cpi[0];
            scpv[wm * 128 + cidx + 1] = cpv[1]; scpi[wm * 128 + cidx + 1] = cpi[1];
            scnv[wm * 128 + cidx] = cnv[0]; scni[wm * 128 + cidx] = cni[0];
            scnv[wm * 128 + cidx + 1] = cnv[1]; scni[wm * 128 + cidx + 1] = cni[1];
        }
    }

    // row partials across the 4 lanes sharing each row
    #pragma unroll
    for (int mi = 0; mi < 2; mi++)
        #pragma unroll
        for (int hb = 0; hb < 2; hb++) {
            #pragma unroll
            for (int off = 1; off <= 2; off <<= 1) {
                redmaxi(rpv[mi][hb], rpi[mi][hb], off);
                redmini(rnv[mi][hb], rni[mi][hb], off);
            }
        }
    float* srpv = (float*)(smem + SM_RPV);
    int*   srpi = (int*)(smem + SM_RPI);
    float* srnv = (float*)(smem + SM_RNV);
    int*   srni = (int*)(smem + SM_RNI);
    if ((lane & 3) == 0) {
        const int gid = lane >> 2;
        #pragma unroll
        for (int mi = 0; mi < 2; mi++)
            #pragma unroll
            for (int hb = 0; hb < 2; hb++) {
                const int row = wm * 32 + mi * 16 + hb * 8 + gid;
                srpv[wn * 128 + row] = rpv[mi][hb]; srpi[wn * 128 + row] = rpi[mi][hb];
                srnv[wn * 128 + row] = rnv[mi][hb]; srni[wn * 128 + row] = rni[mi][hb];
            }
    }
    __syncthreads();
    if (tid < 128) {
        // row anchors (block ti)
        float pv = srpv[tid]; int pi = srpi[tid];
        if (srpv[128 + tid] > pv) { pv = srpv[128 + tid]; pi = srpi[128 + tid]; }
        float nv = srnv[tid]; int nidx = srni[tid];
        if (srnv[128 + tid] < nv) { nv = srnv[128 + tid]; nidx = srni[128 + tid]; }
        if (pv > -1e8f) atomicMax(&g_pos_pack[i0 + tid], packmax(pv, pi));
        if (nv < 1e8f)  atomicMin(&g_neg_pack[i0 + tid], packmin(nv, nidx));
        // column anchors (block tj) via symmetry
        if (ti != tj) {
            float cpv = scpv[tid]; int cpi = scpi[tid];
            float cnv = scnv[tid]; int cni = scni[tid];
            #pragma unroll
            for (int q = 1; q < 4; q++) {
                if (scpv[q * 128 + tid] > cpv) { cpv = scpv[q * 128 + tid]; cpi = scpi[q * 128 + tid]; }
                if (scnv[q * 128 + tid] < cnv) { cnv = scnv[q * 128 + tid]; cni = scni[q * 128 + tid]; }
            }
            if (cpv > -1e8f) atomicMax(&g_pos_pack[j0 + tid], packmax(cpv, cpi));
            if (cnv < 1e8f)  atomicMin(&g_neg_pack[j0 + tid], packmin(cnv, cni));
        }
    }
}

// ====================== 3) exact rescore + finalize ======================
#define CBLOCKS 256
__global__ void combine_kernel(const float* __restrict__ emb, float* __restrict__ out) {
    const int tid = threadIdx.x;
    const int lane = tid & 31, w = tid >> 5;
    float lsum = 0.0f;
    int lcnt = 0;
    #pragma unroll
    for (int rr = 0; rr < 4; rr++) {
        const int row = blockIdx.x * 32 + w * 4 + rr;
        const u64 pp = g_pos_pack[row];
        const u64 np = g_neg_pack[row];
        if (pp != 0ull && np != 0xFFFFFFFFFFFFFFFFull) {
            const int pidx = (int)(uint32_t)(pp & 0xFFFFFFFFull);
            const int nidx = (int)(uint32_t)(np & 0xFFFFFFFFull);
            const float4* pa = (const float4*)&emb[(size_t)row * D];
            const float4* px = (const float4*)&emb[(size_t)pidx * D];
            const float4* pn = (const float4*)&emb[(size_t)nidx * D];
            const float4 a0 = pa[lane], a1 = pa[lane + 32];
            const float4 p0 = px[lane], p1 = px[lane + 32];
            const float4 n0 = pn[lane], n1 = pn[lane + 32];
            float dp = a0.x*p0.x + a0.y*p0.y + a0.z*p0.z + a0.w*p0.w
                     + a1.x*p1.x + a1.y*p1.y + a1.z*p1.z + a1.w*p1.w;
            float dn = a0.x*n0.x + a0.y*n0.y + a0.z*n0.z + a0.w*n0.w
                     + a1.x*n1.x + a1.y*n1.y + a1.z*n1.z + a1.w*n1.w;
            #pragma unroll
            for (int o = 16; o > 0; o >>= 1) {
                dp += __shfl_xor_sync(0xffffffffu, dp, o);
                dn += __shfl_xor_sync(0xffffffffu, dn, o);
            }
            if (lane == 0) {
                const float inva = g_invnorm[row];
                const float dist_p = fmaxf(1.0f - dp * inva * g_invnorm[pidx], 0.0f);
                const float dist_n = fmaxf(1.0f - dn * inva * g_invnorm[nidx], 0.0f);
                lsum += fmaxf(dist_p - dist_n + 1.0f, 0.0f);  // MARGIN = 1.0
                lcnt += 1;
            }
        }
    }
    if (lane == 0 && lcnt > 0) {
        atomicAdd(&g_sum, lsum);
        atomicAdd(&g_cnt, lcnt);
    }
    __syncthreads();
    if (tid == 0) {
        __threadfence();
        const unsigned int rank = atomicAdd(&g_done, 1u);
        if (rank == CBLOCKS - 1) {
            const float total = atomicAdd(&g_sum, 0.0f);
            const int c = atomicAdd(&g_cnt, 0);
            const float cf = (float)c;
            out[0] = (cf > 0.0f) ? (total / fmaxf(cf, 1.0f)) : 0.0f;
        }
    }
}

// ======================================================================
extern "C" void kernel_launch(void* const* d_in, const int* in_sizes, int n_in,
                              void* d_out, int out_size) {
    const float* emb = (const float*)d_in[0];
    const int* labels = (const int*)d_in[1];
    float* out = (float*)d_out;

    cudaFuncSetAttribute(tile_kernel, cudaFuncAttributeMaxDynamicSharedMemorySize, SMEM_TOTAL);

    normalize_kernel<<<B / 8, 256>>>(emb);
    tile_kernel<<<NCTA, 256, SMEM_TOTAL>>>(labels);
    combine_kernel<<<CBLOCKS, 256>>>(emb, out);
}

// round 9
// speedup vs baseline: 1.4034x; 1.4034x over previous
#include <cuda_runtime.h>
#include <cuda_fp16.h>
#include <cstdint>

#define B 8192
#define D 256
#define NT 64
#define NCTA (NT * (NT + 1) / 2)  // 2080 upper-triangular tiles

__device__ __half g_xh[B * D];
__device__ unsigned int g_pos_bits[B];   // bits of (posmax + 1.0f); 0 = none
__device__ unsigned int g_neg_bits[B];   // bits of negmin; init = bits(1e9f)
__device__ float g_sum;
__device__ int   g_cnt;
__device__ unsigned int g_done;

// ---- dynamic smem layout (bytes)
#define SM_A     0                 // 8 slabs x [128][32] halves = 65536
#define SM_B0    65536             // 8192
#define SM_B1    73728             // 8192
#define SM_JLAB  81920             // 512
#define SM_RPOS  82432             // [2][128] f32 = 1024
#define SM_RNEG  83456             // 1024
#define SM_CPOS  84480             // [4][128] f32 = 2048
#define SM_CNEG  86528             // 2048
#define SMEM_TOTAL 88576

__device__ __forceinline__ uint32_t smem_u32(const void* p) {
    uint32_t a;
    asm("{ .reg .u64 t; cvta.to.shared.u64 t, %1; cvt.u32.u64 %0, t; }" : "=r"(a) : "l"(p));
    return a;
}

__device__ __forceinline__ uint32_t swz(int r, int c) {
    return (uint32_t)(r * 64 + ((c ^ ((r >> 1) & 3)) << 4));
}

#define CP_ASYNC16(dst, src) \
    asm volatile("cp.async.cg.shared.global [%0], [%1], 16;" :: "r"(dst), "l"(src) : "memory")
#define CP_COMMIT() asm volatile("cp.async.commit_group;" ::: "memory")

__device__ __forceinline__ void ldsm_x4(uint32_t* f, uint32_t addr) {
    asm volatile("ldmatrix.sync.aligned.m8n8.x4.shared.b16 {%0,%1,%2,%3}, [%4];"
                 : "=r"(f[0]), "=r"(f[1]), "=r"(f[2]), "=r"(f[3]) : "r"(addr));
}

__device__ __forceinline__ void mma16816(float* d, const uint32_t* a, uint32_t b0, uint32_t b1) {
    asm volatile(
        "mma.sync.aligned.m16n8k16.row.col.f32.f16.f16.f32 "
        "{%0,%1,%2,%3}, {%4,%5,%6,%7}, {%8,%9}, {%0,%1,%2,%3};"
        : "+f"(d[0]), "+f"(d[1]), "+f"(d[2]), "+f"(d[3])
        : "r"(a[0]), "r"(a[1]), "r"(a[2]), "r"(a[3]), "r"(b0), "r"(b1));
}

// ====================== 1) normalize -> fp16 (4 rows per warp) + init ======================
__global__ void normalize_kernel(const float* __restrict__ x) {
    const int gid = blockIdx.x * 256 + threadIdx.x;
    // init mining sinks (grid is 256 blocks x 256 threads = 65536 >= B)
    if (gid < B) {
        g_pos_bits[gid] = 0u;
        g_neg_bits[gid] = __float_as_uint(1e9f);
    }
    if (gid == 0) { g_sum = 0.0f; g_cnt = 0; g_done = 0u; }

    const int warp = gid >> 5;          // 2048 warps, 4 rows each
    const int lane = threadIdx.x & 31;
    const int row0 = warp * 4;

    float4 a[4], b[4];
    #pragma unroll
    for (int r = 0; r < 4; r++) {
        const float4* s = (const float4*)&x[(size_t)(row0 + r) * D];
        a[r] = s[lane];
        b[r] = s[lane + 32];
    }
    float ss[4];
    #pragma unroll
    for (int r = 0; r < 4; r++)
        ss[r] = a[r].x*a[r].x + a[r].y*a[r].y + a[r].z*a[r].z + a[r].w*a[r].w
              + b[r].x*b[r].x + b[r].y*b[r].y + b[r].z*b[r].z + b[r].w*b[r].w;
    #pragma unroll
    for (int o = 16; o > 0; o >>= 1) {
        #pragma unroll
        for (int r = 0; r < 4; r++) ss[r] += __shfl_xor_sync(0xffffffffu, ss[r], o);
    }
    #pragma unroll
    for (int r = 0; r < 4; r++) {
        const float inv = 1.0f / fmaxf(sqrtf(ss[r]), 1e-12f);
        uint2 lo, hi;
        __half2 h;
        h = __floats2half2_rn(a[r].x * inv, a[r].y * inv); lo.x = *(uint32_t*)&h;
        h = __floats2half2_rn(a[r].z * inv, a[r].w * inv); lo.y = *(uint32_t*)&h;
        h = __floats2half2_rn(b[r].x * inv, b[r].y * inv); hi.x = *(uint32_t*)&h;
        h = __floats2half2_rn(b[r].z * inv, b[r].w * inv); hi.y = *(uint32_t*)&h;
        uint2* dst = (uint2*)&g_xh[(size_t)(row0 + r) * D];
        dst[lane] = lo;
        dst[lane + 32] = hi;
    }
}

// ====================== 2) upper-triangular fused tile kernel ======================
__global__ __launch_bounds__(256, 2) void tile_kernel(const int* __restrict__ labels) {
    const int g = blockIdx.x;
    int ti = (int)((129.0f - sqrtf(16641.0f - 8.0f * (float)g)) * 0.5f);
    while ((ti + 1) * (129 - (ti + 1)) / 2 <= g) ti++;
    while (ti * (129 - ti) / 2 > g) ti--;
    const int tj = ti + (g - ti * (129 - ti) / 2);

    extern __shared__ char smem[];
    const uint32_t sb = smem_u32(smem);
    const int tid = threadIdx.x;
    const int lane = tid & 31, wid = tid >> 5;
    const int wm = wid & 3, wn = wid >> 2;     // warp grid 4(m) x 2(n)
    const int i0 = ti * 128;
    const int j0 = tj * 128;

    if (tid < 128) ((int*)(smem + SM_JLAB))[tid] = labels[j0 + tid];

    // ---- prologue: A tile (128 rows x 256 halves) into 8 k-slabs of [128][32]
    #pragma unroll
    for (int q = 0; q < 16; q++) {
        const int gg = q * 256 + tid;
        const int slab = gg >> 9, w = gg & 511, r = w >> 2, c = w & 3;
        CP_ASYNC16(sb + SM_A + slab * 8192 + swz(r, c),
                   &g_xh[(size_t)(i0 + r) * D + slab * 32 + c * 8]);
    }
    CP_COMMIT();

    // B slab kk=0 -> buf0
    #pragma unroll
    for (int q = 0; q < 2; q++) {
        const int w = q * 256 + tid, r = w >> 2, c = w & 3;
        CP_ASYNC16(sb + SM_B0 + swz(r, c), &g_xh[(size_t)(j0 + r) * D + c * 8]);
    }
    CP_COMMIT();

    // per-lane ldmatrix offsets
    const int lr = (lane & 7) + ((lane >> 3) & 1) * 8;
    const int lc = lane >> 4;
    uint32_t a_off[2][2], b_off[4][2];
    #pragma unroll
    for (int mi = 0; mi < 2; mi++) {
        const int rA = wm * 32 + mi * 16 + lr;
        #pragma unroll
        for (int ks = 0; ks < 2; ks++) a_off[mi][ks] = swz(rA, 2 * ks + lc);
    }
    #pragma unroll
    for (int pr = 0; pr < 4; pr++) {
        const int rB = wn * 64 + pr * 16 + lr;
        #pragma unroll
        for (int ks = 0; ks < 2; ks++) b_off[pr][ks] = swz(rB, 2 * ks + lc);
    }

    int labm[2][2];
    #pragma unroll
    for (int mi = 0; mi < 2; mi++)
        #pragma unroll
        for (int hb = 0; hb < 2; hb++)
            labm[mi][hb] = __ldg(&labels[i0 + wm * 32 + mi * 16 + hb * 8 + (lane >> 2)]);

    float d[2][8][4];
    #pragma unroll
    for (int mi = 0; mi < 2; mi++)
        #pragma unroll
        for (int ni = 0; ni < 8; ni++)
            #pragma unroll
            for (int e = 0; e < 4; e++) d[mi][ni][e] = 0.0f;

    #pragma unroll
    for (int kk = 0; kk < 8; kk++) {
        if (kk < 7) {
            const uint32_t buf = sb + ((kk & 1) ? SM_B0 : SM_B1);
            #pragma unroll
            for (int q = 0; q < 2; q++) {
                const int w = q * 256 + tid, r = w >> 2, c = w & 3;
                CP_ASYNC16(buf + swz(r, c),
                           &g_xh[(size_t)(j0 + r) * D + (kk + 1) * 32 + c * 8]);
            }
            CP_COMMIT();
            asm volatile("cp.async.wait_group 1;" ::: "memory");
        } else {
            asm volatile("cp.async.wait_group 0;" ::: "memory");
        }
        __syncthreads();

        const uint32_t sa = sb + SM_A + kk * 8192;
        const uint32_t sbuf = sb + ((kk & 1) ? SM_B1 : SM_B0);
        #pragma unroll
        for (int ks = 0; ks < 2; ks++) {
            uint32_t a[2][4];
            ldsm_x4(a[0], sa + a_off[0][ks]);
            ldsm_x4(a[1], sa + a_off[1][ks]);
            uint32_t bf[4][4];
            #pragma unroll
            for (int pr = 0; pr < 4; pr++) ldsm_x4(bf[pr], sbuf + b_off[pr][ks]);
            #pragma unroll
            for (int mi = 0; mi < 2; mi++)
                #pragma unroll
                for (int pr = 0; pr < 4; pr++)
                    #pragma unroll
                    for (int sub = 0; sub < 2; sub++)
                        mma16816(d[mi][pr * 2 + sub], a[mi], bf[pr][sub], bf[pr][sub + 2]);
        }
        __syncthreads();
    }

    // ================= fused epilogue: row + column mining =================
    const int* jl = (const int*)(smem + SM_JLAB);
    float* scpos = (float*)(smem + SM_CPOS);
    float* scneg = (float*)(smem + SM_CNEG);

    float posmax[2][2], negmin[2][2];
    #pragma unroll
    for (int mi = 0; mi < 2; mi++)
        #pragma unroll
        for (int hb = 0; hb < 2; hb++) { posmax[mi][hb] = -1e9f; negmin[mi][hb] = 1e9f; }

    #pragma unroll
    for (int ni = 0; ni < 8; ni++) {
        const int colb = wn * 64 + ni * 8 + (lane & 3) * 2;
        const int l0 = jl[colb], l1 = jl[colb + 1];
        const int n0 = j0 + colb;
        float cp[2] = {-1e9f, -1e9f}, cn[2] = {1e9f, 1e9f};
        #pragma unroll
        for (int mi = 0; mi < 2; mi++) {
            #pragma unroll
            for (int e = 0; e < 4; e++) {
                const int hb = e >> 1, c01 = e & 1;
                const int m = i0 + wm * 32 + mi * 16 + hb * 8 + (lane >> 2);
                const int n = n0 + c01;
                const int ln = c01 ? l1 : l0;
                const float dist = fmaxf(1.0f - d[mi][ni][e], 0.0f);
                if (ln == labm[mi][hb]) {
                    if (m != n) {
                        posmax[mi][hb] = fmaxf(posmax[mi][hb], dist);
                        cp[c01] = fmaxf(cp[c01], dist);
                    }
                } else {
                    negmin[mi][hb] = fminf(negmin[mi][hb], dist);
                    cn[c01] = fminf(cn[c01], dist);
                }
            }
        }
        #pragma unroll
        for (int off = 4; off <= 16; off <<= 1) {
            cp[0] = fmaxf(cp[0], __shfl_xor_sync(0xffffffffu, cp[0], off));
            cp[1] = fmaxf(cp[1], __shfl_xor_sync(0xffffffffu, cp[1], off));
            cn[0] = fminf(cn[0], __shfl_xor_sync(0xffffffffu, cn[0], off));
            cn[1] = fminf(cn[1], __shfl_xor_sync(0xffffffffu, cn[1], off));
        }
        if (lane < 4) {
            const int cidx = wn * 64 + ni * 8 + lane * 2;
            scpos[wm * 128 + cidx]     = cp[0];
            scpos[wm * 128 + cidx + 1] = cp[1];
            scneg[wm * 128 + cidx]     = cn[0];
            scneg[wm * 128 + cidx + 1] = cn[1];
        }
    }

    // reduce row partials across the 4 lanes sharing each row
    #pragma unroll
    for (int mi = 0; mi < 2; mi++)
        #pragma unroll
        for (int hb = 0; hb < 2; hb++) {
            #pragma unroll
            for (int off = 1; off <= 2; off <<= 1) {
                posmax[mi][hb] = fmaxf(posmax[mi][hb], __shfl_xor_sync(0xffffffffu, posmax[mi][hb], off));
                negmin[mi][hb] = fminf(negmin[mi][hb], __shfl_xor_sync(0xffffffffu, negmin[mi][hb], off));
            }
        }
    float* srpos = (float*)(smem + SM_RPOS);
    float* srneg = (float*)(smem + SM_RNEG);
    if ((lane & 3) == 0) {
        const int gid = lane >> 2;
        #pragma unroll
        for (int mi = 0; mi < 2; mi++)
            #pragma unroll
            for (int hb = 0; hb < 2; hb++) {
                const int row = wm * 32 + mi * 16 + hb * 8 + gid;
                srpos[wn * 128 + row] = posmax[mi][hb];
                srneg[wn * 128 + row] = negmin[mi][hb];
            }
    }
    __syncthreads();
    if (tid < 128) {
        // row anchors (block ti)
        const float pv = fmaxf(srpos[tid], srpos[128 + tid]);
        const float nv = fminf(srneg[tid], srneg[128 + tid]);
        if (pv > -1e8f) atomicMax(&g_pos_bits[i0 + tid], __float_as_uint(pv + 1.0f));
        if (nv < 1e8f)  atomicMin(&g_neg_bits[i0 + tid], __float_as_uint(nv));
        // column anchors (block tj) via symmetry (skip on diagonal)
        if (ti != tj) {
            const float cp = fmaxf(fmaxf(scpos[tid], scpos[128 + tid]),
                                   fmaxf(scpos[256 + tid], scpos[384 + tid]));
            const float cn = fminf(fminf(scneg[tid], scneg[128 + tid]),
                                   fminf(scneg[256 + tid], scneg[384 + tid]));
            if (cp > -1e8f) atomicMax(&g_pos_bits[j0 + tid], __float_as_uint(cp + 1.0f));
            if (cn < 1e8f)  atomicMin(&g_neg_bits[j0 + tid], __float_as_uint(cn));
        }
    }
}

// ====================== 3) combine + fused finalize ======================
#define CBLOCKS 32
__global__ void combine_kernel(float* __restrict__ out) {
    const int row = blockIdx.x * 256 + threadIdx.x;
    const float pf = __uint_as_float(g_pos_bits[row]);
    const float nf = __uint_as_float(g_neg_bits[row]);
    const bool valid = (pf >= 1.0f) && (nf < 1e8f);
    const float per = valid ? fmaxf((pf - 1.0f) - nf + 1.0f, 0.0f) : 0.0f;  // MARGIN = 1.0
    const int cnt = valid ? 1 : 0;

    __shared__ float ss[256];
    __shared__ int sc[256];
    const int t = threadIdx.x;
    ss[t] = per; sc[t] = cnt;
    __syncthreads();
    #pragma unroll
    for (int s = 128; s > 0; s >>= 1) {
        if (t < s) { ss[t] += ss[t + s]; sc[t] += sc[t + s]; }
        __syncthreads();
    }
    if (t == 0) {
        atomicAdd(&g_sum, ss[0]);
        atomicAdd(&g_cnt, sc[0]);
        __threadfence();
        const unsigned int rank = atomicAdd(&g_done, 1u);
        if (rank == CBLOCKS - 1) {
            const float total = atomicAdd(&g_sum, 0.0f);
            const int c = atomicAdd(&g_cnt, 0);
            const float cf = (float)c;
            out[0] = (cf > 0.0f) ? (total / fmaxf(cf, 1.0f)) : 0.0f;
        }
    }
}

// ======================================================================
extern "C" void kernel_launch(void* const* d_in, const int* in_sizes, int n_in,
                              void* d_out, int out_size) {
    const float* emb = (const float*)d_in[0];
    const int* labels = (const int*)d_in[1];
    float* out = (float*)d_out;

    cudaFuncSetAttribute(tile_kernel, cudaFuncAttributeMaxDynamicSharedMemorySize, SMEM_TOTAL);

    normalize_kernel<<<256, 256>>>(emb);             // 4 rows/warp
    tile_kernel<<<NCTA, 256, SMEM_TOTAL>>>(labels);
    combine_kernel<<<CBLOCKS, 256>>>(out);
}